// round 9
// baseline (speedup 1.0000x reference)
#include <cuda_runtime.h>
#include <cstdint>

typedef unsigned long long ull;

// Problem constants
#define B_  2048
#define T_  512
#define I_  58
#define KP_ 60          // padded k (multiple of 4)
#define H_  23
#define G_  69          // 3*H
#define GP_ 72          // padded gate dim
#define ROWS_ (B_*T_)   // 1048576
#define NC_  4          // time chunks for gemm/scan pipeline
#define CT_  (T_/NC_)   // 128 timesteps per chunk

// Scratch for x_proj: [B*T][72] padded
__device__ float g_xproj[(size_t)ROWS_ * GP_];
// h carry between scan chunks: [B][32]
__device__ float g_hcarry[(size_t)B_ * 32];

// ---------------- f32x2 helpers ----------------
__device__ __forceinline__ ull pk2(float a, float b) {
    ull r;
    asm("mov.b64 %0, {%1, %2};" : "=l"(r) : "f"(a), "f"(b));
    return r;
}
__device__ __forceinline__ void upk2(ull v, float& a, float& b) {
    asm("mov.b64 {%0, %1}, %2;" : "=f"(a), "=f"(b) : "l"(v));
}
__device__ __forceinline__ ull ffma2(ull a, ull b, ull c) {
    ull d;
    asm("fma.rn.f32x2 %0, %1, %2, %3;" : "=l"(d) : "l"(a), "l"(b), "l"(c));
    return d;
}
__device__ __forceinline__ ull add2(ull a, ull b) {
    ull d;
    asm("add.rn.f32x2 %0, %1, %2;" : "=l"(d) : "l"(a), "l"(b));
    return d;
}
// ---------------- fast transcendentals ----------------
__device__ __forceinline__ float fex2(float x) {
    float y; asm("ex2.approx.f32 %0, %1;" : "=f"(y) : "f"(x)); return y;
}
__device__ __forceinline__ float frcp(float x) {
    float y; asm("rcp.approx.f32 %0, %1;" : "=f"(y) : "f"(x)); return y;
}
__device__ __forceinline__ float fsigmoid(float x) {
    return frcp(1.0f + fex2(-1.4426950408889634f * x));
}
__device__ __forceinline__ float ftanh(float x) {
    float e = fex2(2.8853900817779268f * x);
    return fmaf(-2.0f, frcp(e + 1.0f), 1.0f);
}

// ============================================================================
// Kernel 1: x_proj = task @ W_ih^T + b_ih, for ONE time chunk.
//   Block b handles rows [b*T + t0, +128). (R7 passing math/layout.)
// ============================================================================
__global__ __launch_bounds__(192, 3) void gemm_xproj_kernel(
    const float* __restrict__ task,   // [B*T][58]
    const float* __restrict__ Wih,    // [69][58]
    const float* __restrict__ bih,    // [69]
    int t0)                           // chunk start timestep
{
    __shared__ __align__(16) char sraw[128 * KP_ * 4 + KP_ * 36 * 8];
    float* xs = reinterpret_cast<float*>(sraw);
    ull*   ws = reinterpret_cast<ull*>(sraw + 128 * KP_ * 4);
    __shared__ __align__(16) ull bs[36];

    const int tid = threadIdx.x;
    const size_t rowbase = (size_t)blockIdx.x * T_ + t0;

    {
        const float4* src = reinterpret_cast<const float4*>(task + rowbase * I_);
        #pragma unroll
        for (int it = 0; it < 10; it++) {
            int v = tid + it * 192;
            if (it < 9 || tid < 128) {
                float4 f = src[v];
                int e = 4 * v;
                int r = e / I_, c = e - r * I_;
                float vals[4] = {f.x, f.y, f.z, f.w};
                #pragma unroll
                for (int q = 0; q < 4; q++) {
                    int rr = r, cc = c + q;
                    if (cc >= I_) { rr += 1; cc -= I_; }
                    xs[rr * KP_ + cc] = vals[q];
                }
            }
        }
        for (int i = tid; i < 256; i += 192) {
            int r = i >> 1, c = I_ + (i & 1);
            xs[r * KP_ + c] = 0.0f;
        }
    }
    for (int i = tid; i < KP_ * 36; i += 192) {
        int k = i / 36, p = i - 36 * k;
        int g0 = 2 * p;
        float w0 = (k < I_ && g0     < G_) ? Wih[g0 * I_ + k]       : 0.0f;
        float w1 = (k < I_ && g0 + 1 < G_) ? Wih[(g0 + 1) * I_ + k] : 0.0f;
        float2 wp = make_float2(w0, w1);
        ws[i] = *reinterpret_cast<ull*>(&wp);
    }
    if (tid < 36) {
        int g0 = 2 * tid;
        float b0 = (g0     < G_) ? bih[g0]     : 0.0f;
        float b1 = (g0 + 1 < G_) ? bih[g0 + 1] : 0.0f;
        float2 bp = make_float2(b0, b1);
        bs[tid] = *reinterpret_cast<ull*>(&bp);
    }
    __syncthreads();

    const int gg = tid % 6;
    const int rg = tid / 6;
    const int r0 = rg * 4;
    const ull* wbase = ws + gg * 6;
    const float* xbase = xs + r0 * KP_;

    ull acc[4][6];
    #pragma unroll
    for (int p = 0; p < 6; p++) {
        ull bb = bs[gg * 6 + p];
        acc[0][p] = bb; acc[1][p] = bb; acc[2][p] = bb; acc[3][p] = bb;
    }

    #pragma unroll
    for (int kc = 0; kc < KP_ / 4; kc++) {
        float4 xq[4];
        #pragma unroll
        for (int i = 0; i < 4; i++)
            xq[i] = *reinterpret_cast<const float4*>(xbase + i * KP_ + kc * 4);

        #pragma unroll
        for (int kk = 0; kk < 4; kk++) {
            ull X[4];
            #pragma unroll
            for (int i = 0; i < 4; i++) {
                float xv = (kk == 0) ? xq[i].x : (kk == 1) ? xq[i].y
                         : (kk == 2) ? xq[i].z : xq[i].w;
                X[i] = pk2(xv, xv);
            }
            const ulonglong2* wk =
                reinterpret_cast<const ulonglong2*>(wbase + (kc * 4 + kk) * 36);
            ulonglong2 wA = wk[0], wB = wk[1], wC = wk[2];
            #pragma unroll
            for (int i = 0; i < 4; i++) {
                acc[i][0] = ffma2(X[i], wA.x, acc[i][0]);
                acc[i][1] = ffma2(X[i], wA.y, acc[i][1]);
                acc[i][2] = ffma2(X[i], wB.x, acc[i][2]);
                acc[i][3] = ffma2(X[i], wB.y, acc[i][3]);
                acc[i][4] = ffma2(X[i], wC.x, acc[i][4]);
                acc[i][5] = ffma2(X[i], wC.y, acc[i][5]);
            }
        }
    }

    __syncthreads();
    ull* os = reinterpret_cast<ull*>(sraw);
    #pragma unroll
    for (int i = 0; i < 4; i++) {
        #pragma unroll
        for (int p = 0; p < 6; p++) {
            os[(r0 + i) * 36 + gg * 6 + p] = acc[i][p];
        }
    }
    __syncthreads();
    {
        const float4* src = reinterpret_cast<const float4*>(sraw);
        float4* dst = reinterpret_cast<float4*>(g_xproj + rowbase * GP_);
        #pragma unroll
        for (int it = 0; it < 12; it++) {
            int idx = tid + it * 192;
            dst[idx] = src[idx];
        }
    }
}

// ============================================================================
// Kernel 2: GRU scan for ONE time chunk of CT_=128 steps. (R7 skeleton.)
// ============================================================================
__global__ __launch_bounds__(128, 4) void gru_scan_kernel(
    const float* __restrict__ Whh,    // [69][23]
    const float* __restrict__ bhh,    // [69]
    const float* __restrict__ piw,    // [23]
    const float* __restrict__ pib,    // [23]
    float* __restrict__ out_action,   // [B][T][23]
    float* __restrict__ out_hidden,   // [B][23]
    int t0)                           // chunk start timestep
{
    __shared__ __align__(16) float hsm[4][2][32];

    const int j  = threadIdx.x & 31;
    const int w  = threadIdx.x >> 5;
    const int b  = blockIdx.x * 4 + w;
    const int jc = (j < H_) ? j : (H_ - 1);
    const bool act = (j < H_);
    const bool last = (t0 + CT_ == T_);

    ull WR[12], WZ[12], WN[12];
    {
        const float* wr = Whh + (size_t)jc * H_;
        const float* wz = Whh + (size_t)(H_ + jc) * H_;
        const float* wn = Whh + (size_t)(2 * H_ + jc) * H_;
        #pragma unroll
        for (int m = 0; m < 11; m++) {
            WR[m] = pk2(wr[2 * m], wr[2 * m + 1]);
            WZ[m] = pk2(wz[2 * m], wz[2 * m + 1]);
            WN[m] = pk2(wn[2 * m], wn[2 * m + 1]);
        }
        WR[11] = pk2(wr[22], bhh[jc]);
        WZ[11] = pk2(wz[22], bhh[H_ + jc]);
        WN[11] = pk2(wn[22], bhh[2 * H_ + jc]);
    }
    const float pw = piw[jc], pb = pib[jc];

    // initial h for this chunk: zeros for chunk 0, else carry
    float h = 0.0f;
    if (t0 != 0 && act) h = g_hcarry[(size_t)b * 32 + j];
    {
        float v = (j == 23) ? 1.0f : (act ? h : 0.0f);
        hsm[w][0][j] = v;
        hsm[w][1][j] = v;
    }
    __syncwarp();

    const float* xp = g_xproj + ((size_t)b * T_ + t0) * GP_;
    float* outp = out_action + ((size_t)b * T_ + t0) * H_;
    const int o0 = jc, o1 = H_ + jc, o2 = 2 * H_ + jc;

    float cur[12];
    #pragma unroll
    for (int s = 0; s < 4; s++) {
        const float* xr = xp + s * GP_;
        cur[3 * s + 0] = xr[o0];
        cur[3 * s + 1] = xr[o1];
        cur[3 * s + 2] = xr[o2];
    }

    #pragma unroll 2
    for (int tb = 0; tb < CT_; tb += 4) {
        const float* xn_ = xp + (size_t)((tb + 4 < CT_) ? tb + 4 : CT_ - 4) * GP_;
        #pragma unroll
        for (int s = 0; s < 4; s++) {
            const ulonglong2* hq =
                reinterpret_cast<const ulonglong2*>(hsm[w][s & 1]);
            ull aR0 = 0, aR1 = 0, aZ0 = 0, aZ1 = 0, aN0 = 0, aN1 = 0;
            #pragma unroll
            for (int m = 0; m < 6; m++) {
                ulonglong2 q = hq[m];
                aR0 = ffma2(WR[2 * m],     q.x, aR0);
                aR1 = ffma2(WR[2 * m + 1], q.y, aR1);
                aZ0 = ffma2(WZ[2 * m],     q.x, aZ0);
                aZ1 = ffma2(WZ[2 * m + 1], q.y, aZ1);
                aN0 = ffma2(WN[2 * m],     q.x, aN0);
                aN1 = ffma2(WN[2 * m + 1], q.y, aN1);
            }
            ull aR = add2(aR0, aR1);
            ull aZ = add2(aZ0, aZ1);
            ull aN = add2(aN0, aN1);
            float rl, rh, zl, zh, nl, nh;
            upk2(aR, rl, rh); upk2(aZ, zl, zh); upk2(aN, nl, nh);

            float r = fsigmoid(cur[3 * s + 0] + (rl + rh));
            float z = fsigmoid(cur[3 * s + 1] + (zl + zh));
            float n = ftanh(fmaf(r, nl + nh, cur[3 * s + 2]));
            float hnew = fmaf(z, h - n, n);        // (1-z)*n + z*h

            if (act) hsm[w][(s + 1) & 1][j] = hnew;
            __syncwarp();

            if (act) outp[(size_t)(tb + s) * H_ + j] = fmaf(pw, hnew, pb);
            h = hnew;

            cur[3 * s + 0] = xn_[s * GP_ + o0];
            cur[3 * s + 1] = xn_[s * GP_ + o1];
            cur[3 * s + 2] = xn_[s * GP_ + o2];
        }
    }

    if (act) {
        g_hcarry[(size_t)b * 32 + j] = h;
        if (last) out_hidden[(size_t)b * H_ + j] = h;
    }
}

// ============================================================================
// Launch: pipeline gemm chunks (capture stream) with scan chunks (side stream)
// joined by events. Streams/events are created ONCE on the first call (the
// uncaptured correctness run) and reused during graph capture — resource
// creation never happens while a capture is active.
// ============================================================================
extern "C" void kernel_launch(void* const* d_in, const int* in_sizes, int n_in,
                              void* d_out, int out_size) {
    const float* task = (const float*)d_in[0];  // (2048,512,58)
    const float* Wih  = (const float*)d_in[1];  // (69,58)
    const float* Whh  = (const float*)d_in[2];  // (69,23)
    const float* bih  = (const float*)d_in[3];  // (69)
    const float* bhh  = (const float*)d_in[4];  // (69)
    const float* piw  = (const float*)d_in[5];  // (23)
    const float* pib  = (const float*)d_in[6];  // (23)

    float* out = (float*)d_out;
    float* action = out;                                  // B*T*H
    float* hidden = out + (size_t)B_ * T_ * H_;           // B*H

    // One-time resource init (first call is outside capture).
    static cudaStream_t s1 = nullptr;
    static cudaEvent_t evg[NC_];
    static cudaEvent_t evdone = nullptr;
    if (s1 == nullptr) {
        cudaStreamCreateWithFlags(&s1, cudaStreamNonBlocking);
        for (int c = 0; c < NC_; c++)
            cudaEventCreateWithFlags(&evg[c], cudaEventDisableTiming);
        cudaEventCreateWithFlags(&evdone, cudaEventDisableTiming);
    }

    for (int c = 0; c < NC_; c++) {
        int t0 = c * CT_;
        gemm_xproj_kernel<<<B_, 192>>>(task, Wih, bih, t0);
        cudaEventRecord(evg[c], 0);
        cudaStreamWaitEvent(s1, evg[c], 0);
        gru_scan_kernel<<<B_ / 4, 128, 0, s1>>>(Whh, bhh, piw, pib,
                                                action, hidden, t0);
    }
    cudaEventRecord(evdone, s1);
    cudaStreamWaitEvent(0, evdone, 0);
}